// round 14
// baseline (speedup 1.0000x reference)
#include <cuda_runtime.h>
#include <cfloat>
#include <cstdint>

#define B_   32
#define N_   4096
#define S_   512
#define K_   16
#define NPTS (B_ * S_ * K_)
#define NROW (B_ * S_)

__device__ __forceinline__ float sqdist3(float dx, float dy, float dz) {
    return __fadd_rn(__fadd_rn(__fmul_rn(dx, dx), __fmul_rn(dy, dy)), __fmul_rn(dz, dz));
}

// XLA-GPU broadcast-divisor lowering: x / den -> x * reciprocal(den), IEEE rcp + RN mul
__device__ __forceinline__ float div_rcp_rn(float a, float b) {
    float r; asm("rcp.rn.f32 %0, %1;" : "=f"(r) : "f"(b)); return __fmul_rn(a, r);
}

// ---- static scratch ----
__device__ float d_new_xyz[NROW * 3];
__device__ int   d_knn[NROW * K_];
__device__ float d_g0[(size_t)NPTS * 6];
__device__ float d_a1[(size_t)NPTS * 64];
__device__ float d_a2[(size_t)NPTS * 128];
__device__ float d_a3[(size_t)NPTS * 256];
__device__ float d_ft[(size_t)NROW * 256];
__device__ float d_gfv[B_ * 256];
__device__ float d_ft2[(size_t)NROW * 512];
__device__ float d_y1[(size_t)NROW * 512];
__device__ float d_y2[(size_t)NROW * 256];
__device__ float d_y3[(size_t)NROW * 128];
__device__ float d_y4[(size_t)NROW * 12];

// ---- 1. FPS ----
__global__ void __launch_bounds__(1024, 1) k_fps(const float* __restrict__ xyz) {
    const int b = blockIdx.x, tid = threadIdx.x;
    const float* base = xyz + (size_t)b * N_ * 3;
    float px[4], py[4], pz[4], dd[4];
#pragma unroll
    for (int j = 0; j < 4; j++) {
        int i = tid + j * 1024;
        px[j] = base[i * 3 + 0]; py[j] = base[i * 3 + 1]; pz[j] = base[i * 3 + 2];
        dd[j] = 1e10f;
    }
    __shared__ float s_c[3];
    __shared__ float s_v[32];
    __shared__ int   s_i[32];
    __shared__ int   s_far;
    int far = 0;
    for (int t = 0; t < S_; t++) {
        if (tid == (far & 1023)) {
            int j = far >> 10;
            s_c[0] = px[j]; s_c[1] = py[j]; s_c[2] = pz[j];
        }
        __syncthreads();
        float cx = s_c[0], cy = s_c[1], cz = s_c[2];
        if (tid == 0) {
            float* o = d_new_xyz + ((size_t)b * S_ + t) * 3;
            o[0] = cx; o[1] = cy; o[2] = cz;
        }
        float bv = -1.0f; int bi = 0;
#pragma unroll
        for (int j = 0; j < 4; j++) {
            float d  = sqdist3(px[j] - cx, py[j] - cy, pz[j] - cz);
            float nd = fminf(dd[j], d);
            dd[j] = nd;
            if (nd > bv) { bv = nd; bi = tid + j * 1024; }
        }
#pragma unroll
        for (int o = 16; o > 0; o >>= 1) {
            float ov = __shfl_down_sync(0xffffffffu, bv, o);
            int   oi = __shfl_down_sync(0xffffffffu, bi, o);
            if (ov > bv || (ov == bv && oi < bi)) { bv = ov; bi = oi; }
        }
        if ((tid & 31) == 0) { s_v[tid >> 5] = bv; s_i[tid >> 5] = bi; }
        __syncthreads();
        if (tid < 32) {
            bv = s_v[tid]; bi = s_i[tid];
#pragma unroll
            for (int o = 16; o > 0; o >>= 1) {
                float ov = __shfl_down_sync(0xffffffffu, bv, o);
                int   oi = __shfl_down_sync(0xffffffffu, bi, o);
                if (ov > bv || (ov == bv && oi < bi)) { bv = ov; bi = oi; }
            }
            if (tid == 0) s_far = bi;
        }
        __syncthreads();
        far = s_far;
    }
}

// ---- 2. KNN ----
__global__ void __launch_bounds__(256) k_knn(const float* __restrict__ xyz) {
    const int b = blockIdx.y, c0 = blockIdx.x * 64, tid = threadIdx.x;
    const float* base = xyz + (size_t)b * N_ * 3;
    float px[16], py[16], pz[16];
#pragma unroll
    for (int j = 0; j < 16; j++) {
        int i = tid + j * 256;
        px[j] = base[i * 3 + 0]; py[j] = base[i * 3 + 1]; pz[j] = base[i * 3 + 2];
    }
    __shared__ float s_v[8];
    __shared__ int   s_i[8];
    __shared__ int   s_sel;
    for (int s = 0; s < 64; s++) {
        int sc = c0 + s;
        const float* c = d_new_xyz + ((size_t)b * S_ + sc) * 3;
        float cx = c[0], cy = c[1], cz = c[2];
        float d[16];
#pragma unroll
        for (int j = 0; j < 16; j++)
            d[j] = sqdist3(px[j] - cx, py[j] - cy, pz[j] - cz);
        for (int r = 0; r < K_; r++) {
            float bv = FLT_MAX; int bi = 0x7fffffff;
#pragma unroll
            for (int j = 0; j < 16; j++)
                if (d[j] < bv) { bv = d[j]; bi = tid + j * 256; }
#pragma unroll
            for (int o = 16; o > 0; o >>= 1) {
                float ov = __shfl_down_sync(0xffffffffu, bv, o);
                int   oi = __shfl_down_sync(0xffffffffu, bi, o);
                if (ov < bv || (ov == bv && oi < bi)) { bv = ov; bi = oi; }
            }
            if ((tid & 31) == 0) { s_v[tid >> 5] = bv; s_i[tid >> 5] = bi; }
            __syncthreads();
            if (tid == 0) {
                float mv = s_v[0]; int mi = s_i[0];
#pragma unroll
                for (int w = 1; w < 8; w++)
                    if (s_v[w] < mv || (s_v[w] == mv && s_i[w] < mi)) { mv = s_v[w]; mi = s_i[w]; }
                d_knn[((size_t)b * S_ + sc) * K_ + r] = mi;
                s_sel = mi;
            }
            __syncthreads();
            int sel = s_sel;
#pragma unroll
            for (int j = 0; j < 16; j++)
                if (sel == tid + j * 256) d[j] = FLT_MAX;
        }
    }
}

// ---- 3. gather ----
__global__ void __launch_bounds__(256) k_gather(const float* __restrict__ pc) {
    int idx = blockIdx.x * 256 + threadIdx.x;
    int r = idx >> 4, b = r >> 9;
    int gi = d_knn[idx];
    const float* p = pc + ((size_t)b * N_ + gi) * 3;
    const float* c = d_new_xyz + (size_t)r * 3;
    float gx = p[0], gy = p[1], gz = p[2];
    float* o = d_g0 + (size_t)idx * 6;
    o[0] = gx - c[0]; o[1] = gy - c[1]; o[2] = gz - c[2];
    o[3] = gx;        o[4] = gy;        o[5] = gz;
}

// ---- GEMM ----
template <int ACT>
__global__ void __launch_bounds__(256) gemm_v2(const float* __restrict__ A,
                                               const float* __restrict__ W,
                                               const float* __restrict__ bias,
                                               float* __restrict__ C,
                                               int M, int N, int K) {
    __shared__ float Asm[64][17];
    __shared__ float Bsm[16][68];
    const int tid = threadIdx.x;
    const int bm = blockIdx.x * 64, bn = blockIdx.y * 64;
    const int r0 = (tid & 15) * 4, c0 = (tid >> 4) * 4;
    float acc[4][4] = {};
    for (int k0 = 0; k0 < K; k0 += 16) {
#pragma unroll
        for (int p = 0; p < 4; p++) {
            int i = p * 256 + tid;
            int m = i & 63, k = i >> 6;
            Asm[m][k] = (k0 + k < K) ? A[(size_t)(bm + m) * K + (k0 + k)] : 0.0f;
        }
#pragma unroll
        for (int p = 0; p < 4; p++) {
            int i = p * 256 + tid;
            int n = i & 63, k = i >> 6;
            Bsm[k][n] = ((k0 + k < K) && (bn + n < N)) ? W[(size_t)(k0 + k) * N + (bn + n)] : 0.0f;
        }
        __syncthreads();
#pragma unroll
        for (int k = 0; k < 16; k++) {
            float a0 = Asm[r0 + 0][k], a1 = Asm[r0 + 1][k];
            float a2 = Asm[r0 + 2][k], a3 = Asm[r0 + 3][k];
            float b0 = Bsm[k][c0 + 0], b1 = Bsm[k][c0 + 1];
            float b2 = Bsm[k][c0 + 2], b3 = Bsm[k][c0 + 3];
            acc[0][0] += a0 * b0; acc[0][1] += a0 * b1; acc[0][2] += a0 * b2; acc[0][3] += a0 * b3;
            acc[1][0] += a1 * b0; acc[1][1] += a1 * b1; acc[1][2] += a1 * b2; acc[1][3] += a1 * b3;
            acc[2][0] += a2 * b0; acc[2][1] += a2 * b1; acc[2][2] += a2 * b2; acc[2][3] += a2 * b3;
            acc[3][0] += a3 * b0; acc[3][1] += a3 * b1; acc[3][2] += a3 * b2; acc[3][3] += a3 * b3;
        }
        __syncthreads();
    }
#pragma unroll
    for (int i = 0; i < 4; i++) {
        int row = bm + r0 + i;
        if (row >= M) continue;
#pragma unroll
        for (int j = 0; j < 4; j++) {
            int col = bn + c0 + j;
            if (col < N) {
                float v = acc[i][j] + bias[col];
                if (ACT == 1) v = fmaxf(v, 0.0f);
                if (ACT == 2) v = (v > 0.0f) ? v : 0.2f * v;
                C[(size_t)row * N + col] = v;
            }
        }
    }
}

// ---- 4-6. pooling / concat ----
__global__ void __launch_bounds__(256) k_maxk() {
    int idx = blockIdx.x * 256 + threadIdx.x;
    int c = idx & 255;
    size_t r = (size_t)(idx >> 8);
    float m = -FLT_MAX;
    for (int k = 0; k < K_; k++)
        m = fmaxf(m, d_a3[(r * K_ + k) * 256 + c]);
    d_ft[idx] = m;
}

__global__ void __launch_bounds__(256) k_gf() {
    int idx = blockIdx.x * 256 + threadIdx.x;
    int c = idx & 255, b = idx >> 8;
    float m = -FLT_MAX;
    for (int s = 0; s < S_; s++)
        m = fmaxf(m, d_ft[((size_t)b * S_ + s) * 256 + c]);
    d_gfv[idx] = m;
}

__global__ void __launch_bounds__(256) k_cat() {
    size_t idx = (size_t)blockIdx.x * 256 + threadIdx.x;
    int c = (int)(idx & 511);
    size_t r = idx >> 9;
    int b = (int)(r >> 9);
    d_ft2[idx] = (c < 256) ? d_ft[r * 256 + c] : d_gfv[b * 256 + (c - 256)];
}

// ---- 7. sym + Morton (x * rcp.rn(den)) + stable reorder + output ----
__global__ void __launch_bounds__(512) k_final(float* __restrict__ out) {
    const int b = blockIdx.x, tid = threadIdx.x;
    __shared__ float red[512];
    __shared__ float mn3[3], mx3[3];
    __shared__ unsigned long long cod[512];

    const float* cp = d_new_xyz + ((size_t)b * S_ + tid) * 3;
    float p[3] = {cp[0], cp[1], cp[2]};

    for (int ax = 0; ax < 3; ax++) {
        red[tid] = p[ax];
        __syncthreads();
        for (int s = 256; s > 0; s >>= 1) {
            if (tid < s) red[tid] = fminf(red[tid], red[tid + s]);
            __syncthreads();
        }
        if (tid == 0) mn3[ax] = red[0];
        __syncthreads();
        red[tid] = p[ax];
        __syncthreads();
        for (int s = 256; s > 0; s >>= 1) {
            if (tid < s) red[tid] = fmaxf(red[tid], red[tid + s]);
            __syncthreads();
        }
        if (tid == 0) mx3[ax] = red[0];
        __syncthreads();
    }

    unsigned long long code = 0;
#pragma unroll
    for (int ax = 0; ax < 3; ax++) {
        float num = __fsub_rn(p[ax], mn3[ax]);
        float den = __fadd_rn(__fsub_rn(mx3[ax], mn3[ax]), 1e-8f);
        float nrm = div_rcp_rn(num, den);
        long long q = (long long)nrm;   // truncation: 0 or 1
        q *= 65535LL;
        if (q < 0) q = 0;
        if (q > 65535) q = 65535;
        unsigned long long m = (unsigned long long)q;
        m = (m | (m << 8)) & 0x00FF00FFull;
        m = (m | (m << 4)) & 0x0F0F0F0Full;
        m = (m | (m << 2)) & 0x33333333ull;
        m = (m | (m << 1)) & 0x55555555ull;
        code |= m << (2 - ax);
    }
    cod[tid] = code;
    __syncthreads();

    int rank = 0;
    for (int j = 0; j < 512; j++) {
        unsigned long long cj = cod[j];
        rank += (cj < code || (cj == code && j < tid)) ? 1 : 0;
    }

    const float* rr = d_y4 + ((size_t)b * S_ + tid) * 12;
    float s0 = p[0] * rr[0] + p[1] * rr[3] + p[2] * rr[6] + rr[9];
    float s1 = p[0] * rr[1] + p[1] * rr[4] + p[2] * rr[7] + rr[10];
    float s2 = p[0] * rr[2] + p[1] * rr[5] + p[2] * rr[8] + rr[11];

    float* o = out + ((size_t)b * (2 * S_) + 2 * (size_t)rank) * 3;
    o[0] = p[0]; o[1] = p[1]; o[2] = p[2];
    o[3] = s0;   o[4] = s1;   o[5] = s2;
}

// ---- launcher ----
extern "C" void kernel_launch(void* const* d_in, const int* in_sizes, int n_in,
                              void* d_out, int out_size) {
    (void)out_size;
    int map[15];
    {
        const int want[15] = {393216, 384, 64, 8192, 128, 32768, 256,
                              262144, 512, 131072, 256, 32768, 128, 1536, 12};
        bool dict_order = (n_in == 15);
        if (dict_order)
            for (int i = 0; i < 15; i++)
                if (in_sizes[i] != want[i]) { dict_order = false; break; }
        if (dict_order) {
            for (int i = 0; i < 15; i++) map[i] = i;
        } else {
            int used[64] = {0};
            for (int lo = 0; lo < 15; lo++) {
                map[lo] = 0;
                for (int i = 0; i < n_in && i < 64; i++)
                    if (!used[i] && in_sizes[i] == want[lo]) { map[lo] = i; used[i] = 1; break; }
            }
        }
    }
    const float* pc    = (const float*)d_in[map[0]];
    const float* w_sa1 = (const float*)d_in[map[1]];
    const float* b_sa1 = (const float*)d_in[map[2]];
    const float* w_sa2 = (const float*)d_in[map[3]];
    const float* b_sa2 = (const float*)d_in[map[4]];
    const float* w_sa3 = (const float*)d_in[map[5]];
    const float* b_sa3 = (const float*)d_in[map[6]];
    const float* w1 = (const float*)d_in[map[7]];
    const float* b1 = (const float*)d_in[map[8]];
    const float* w2 = (const float*)d_in[map[9]];
    const float* b2 = (const float*)d_in[map[10]];
    const float* w3 = (const float*)d_in[map[11]];
    const float* b3 = (const float*)d_in[map[12]];
    const float* w4 = (const float*)d_in[map[13]];
    const float* b4 = (const float*)d_in[map[14]];
    float* out = (float*)d_out;

    float *g0, *a1, *a2, *a3, *ft2, *y1, *y2, *y3, *y4;
    cudaGetSymbolAddress((void**)&g0,  d_g0);
    cudaGetSymbolAddress((void**)&a1,  d_a1);
    cudaGetSymbolAddress((void**)&a2,  d_a2);
    cudaGetSymbolAddress((void**)&a3,  d_a3);
    cudaGetSymbolAddress((void**)&ft2, d_ft2);
    cudaGetSymbolAddress((void**)&y1,  d_y1);
    cudaGetSymbolAddress((void**)&y2,  d_y2);
    cudaGetSymbolAddress((void**)&y3,  d_y3);
    cudaGetSymbolAddress((void**)&y4,  d_y4);

    k_fps<<<B_, 1024>>>(pc);
    k_knn<<<dim3(8, B_), 256>>>(pc);
    k_gather<<<NPTS / 256, 256>>>(pc);

    gemm_v2<1><<<dim3(NPTS / 64, 1), 256>>>(g0, w_sa1, b_sa1, a1, NPTS, 64, 6);
    gemm_v2<1><<<dim3(NPTS / 64, 2), 256>>>(a1, w_sa2, b_sa2, a2, NPTS, 128, 64);
    gemm_v2<1><<<dim3(NPTS / 64, 4), 256>>>(a2, w_sa3, b_sa3, a3, NPTS, 256, 128);

    k_maxk<<<NROW, 256>>>();
    k_gf<<<B_, 256>>>();
    k_cat<<<NROW * 512 / 256, 256>>>();

    gemm_v2<2><<<dim3(NROW / 64, 8), 256>>>(ft2, w1, b1, y1, NROW, 512, 512);
    gemm_v2<2><<<dim3(NROW / 64, 4), 256>>>(y1, w2, b2, y2, NROW, 256, 512);
    gemm_v2<2><<<dim3(NROW / 64, 2), 256>>>(y2, w3, b3, y3, NROW, 128, 256);
    gemm_v2<0><<<dim3(NROW / 64, 1), 256>>>(y3, w4, b4, y4, NROW, 12, 128);

    k_final<<<B_, 512>>>(out);
}

// round 15
// speedup vs baseline: 1.3855x; 1.3855x over previous
#include <cuda_runtime.h>
#include <cfloat>
#include <cstdint>

#define B_   32
#define N_   4096
#define S_   512
#define K_   16
#define NPTS (B_ * S_ * K_)
#define NROW (B_ * S_)

__device__ __forceinline__ float sqdist3(float dx, float dy, float dz) {
    return __fadd_rn(__fadd_rn(__fmul_rn(dx, dx), __fmul_rn(dy, dy)), __fmul_rn(dz, dz));
}

// XLA-GPU broadcast-divisor lowering: x / den -> x * reciprocal(den)
__device__ __forceinline__ float div_rcp_rn(float a, float b) {
    float r; asm("rcp.rn.f32 %0, %1;" : "=f"(r) : "f"(b)); return __fmul_rn(a, r);
}

// ---- static scratch ----
__device__ float d_new_xyz[NROW * 3];
__device__ int   d_knn[NROW * K_];
__device__ float d_a1[(size_t)NPTS * 64];
__device__ float d_a2[(size_t)NPTS * 128];
__device__ float d_a3[(size_t)NPTS * 256];
__device__ float d_ft[(size_t)NROW * 256];
__device__ float d_gfv[B_ * 256];
__device__ float d_ft2[(size_t)NROW * 512];
__device__ float d_y1[(size_t)NROW * 512];
__device__ float d_y2[(size_t)NROW * 256];
__device__ float d_y3[(size_t)NROW * 128];
__device__ float d_y4[(size_t)NROW * 12];

// ---- 1. FPS ----
__global__ void __launch_bounds__(1024, 1) k_fps(const float* __restrict__ xyz) {
    const int b = blockIdx.x, tid = threadIdx.x;
    const float* base = xyz + (size_t)b * N_ * 3;
    float px[4], py[4], pz[4], dd[4];
#pragma unroll
    for (int j = 0; j < 4; j++) {
        int i = tid + j * 1024;
        px[j] = base[i * 3 + 0]; py[j] = base[i * 3 + 1]; pz[j] = base[i * 3 + 2];
        dd[j] = 1e10f;
    }
    __shared__ float s_c[3];
    __shared__ float s_v[32];
    __shared__ int   s_i[32];
    __shared__ int   s_far;
    int far = 0;
    for (int t = 0; t < S_; t++) {
        if (tid == (far & 1023)) {
            int j = far >> 10;
            s_c[0] = px[j]; s_c[1] = py[j]; s_c[2] = pz[j];
        }
        __syncthreads();
        float cx = s_c[0], cy = s_c[1], cz = s_c[2];
        if (tid == 0) {
            float* o = d_new_xyz + ((size_t)b * S_ + t) * 3;
            o[0] = cx; o[1] = cy; o[2] = cz;
        }
        float bv = -1.0f; int bi = 0;
#pragma unroll
        for (int j = 0; j < 4; j++) {
            float d  = sqdist3(px[j] - cx, py[j] - cy, pz[j] - cz);
            float nd = fminf(dd[j], d);
            dd[j] = nd;
            if (nd > bv) { bv = nd; bi = tid + j * 1024; }
        }
#pragma unroll
        for (int o = 16; o > 0; o >>= 1) {
            float ov = __shfl_down_sync(0xffffffffu, bv, o);
            int   oi = __shfl_down_sync(0xffffffffu, bi, o);
            if (ov > bv || (ov == bv && oi < bi)) { bv = ov; bi = oi; }
        }
        if ((tid & 31) == 0) { s_v[tid >> 5] = bv; s_i[tid >> 5] = bi; }
        __syncthreads();
        if (tid < 32) {
            bv = s_v[tid]; bi = s_i[tid];
#pragma unroll
            for (int o = 16; o > 0; o >>= 1) {
                float ov = __shfl_down_sync(0xffffffffu, bv, o);
                int   oi = __shfl_down_sync(0xffffffffu, bi, o);
                if (ov > bv || (ov == bv && oi < bi)) { bv = ov; bi = oi; }
            }
            if (tid == 0) s_far = bi;
        }
        __syncthreads();
        far = s_far;
    }
}

// ---- 2. KNN ----
__global__ void __launch_bounds__(256) k_knn(const float* __restrict__ xyz) {
    const int b = blockIdx.y, c0 = blockIdx.x * 64, tid = threadIdx.x;
    const float* base = xyz + (size_t)b * N_ * 3;
    float px[16], py[16], pz[16];
#pragma unroll
    for (int j = 0; j < 16; j++) {
        int i = tid + j * 256;
        px[j] = base[i * 3 + 0]; py[j] = base[i * 3 + 1]; pz[j] = base[i * 3 + 2];
    }
    __shared__ float s_v[8];
    __shared__ int   s_i[8];
    __shared__ int   s_sel;
    for (int s = 0; s < 64; s++) {
        int sc = c0 + s;
        const float* c = d_new_xyz + ((size_t)b * S_ + sc) * 3;
        float cx = c[0], cy = c[1], cz = c[2];
        float d[16];
#pragma unroll
        for (int j = 0; j < 16; j++)
            d[j] = sqdist3(px[j] - cx, py[j] - cy, pz[j] - cz);
        for (int r = 0; r < K_; r++) {
            float bv = FLT_MAX; int bi = 0x7fffffff;
#pragma unroll
            for (int j = 0; j < 16; j++)
                if (d[j] < bv) { bv = d[j]; bi = tid + j * 256; }
#pragma unroll
            for (int o = 16; o > 0; o >>= 1) {
                float ov = __shfl_down_sync(0xffffffffu, bv, o);
                int   oi = __shfl_down_sync(0xffffffffu, bi, o);
                if (ov < bv || (ov == bv && oi < bi)) { bv = ov; bi = oi; }
            }
            if ((tid & 31) == 0) { s_v[tid >> 5] = bv; s_i[tid >> 5] = bi; }
            __syncthreads();
            if (tid == 0) {
                float mv = s_v[0]; int mi = s_i[0];
#pragma unroll
                for (int w = 1; w < 8; w++)
                    if (s_v[w] < mv || (s_v[w] == mv && s_i[w] < mi)) { mv = s_v[w]; mi = s_i[w]; }
                d_knn[((size_t)b * S_ + sc) * K_ + r] = mi;
                s_sel = mi;
            }
            __syncthreads();
            int sel = s_sel;
#pragma unroll
            for (int j = 0; j < 16; j++)
                if (sel == tid + j * 256) d[j] = FLT_MAX;
        }
    }
}

// ---- 3. fused gather + sa1 (K=6 -> 64, relu) ----
__global__ void __launch_bounds__(256) k_sa1(const float* __restrict__ pc,
                                             const float* __restrict__ w,
                                             const float* __restrict__ bias) {
    __shared__ float ws[6][64];
    __shared__ float bs[64];
    int tid = threadIdx.x;
    if (tid < 64) bs[tid] = bias[tid];
#pragma unroll
    for (int i = tid; i < 384; i += 256) ws[i >> 6][i & 63] = w[i];
    __syncthreads();

    int idx = blockIdx.x * 256 + tid;       // point index in [0, NPTS)
    int r = idx >> 4, b = r >> 9;
    int gi = d_knn[idx];
    const float* p = pc + ((size_t)b * N_ + gi) * 3;
    const float* c = d_new_xyz + (size_t)r * 3;
    float gx = p[0], gy = p[1], gz = p[2];
    float f[6] = {gx - c[0], gy - c[1], gz - c[2], gx, gy, gz};

    float* o = d_a1 + (size_t)idx * 64;
#pragma unroll
    for (int n4 = 0; n4 < 16; n4++) {
        float4 v;
        float* vv = (float*)&v;
#pragma unroll
        for (int q = 0; q < 4; q++) {
            int n = n4 * 4 + q;
            float acc = bs[n];
#pragma unroll
            for (int j = 0; j < 6; j++) acc += f[j] * ws[j][n];
            vv[q] = fmaxf(acc, 0.0f);
        }
        *(float4*)(o + n4 * 4) = v;
    }
}

// ---- GEMM v3: vectorized, requires K%32==0 && N%64==0, M%64==0 ----
// 64x64 tile, 256 threads, 4x4 microtile, k-major smem, float4 LDS.
template <int ACT>
__global__ void __launch_bounds__(256) gemm_v3(const float* __restrict__ A,
                                               const float* __restrict__ W,
                                               const float* __restrict__ bias,
                                               float* __restrict__ C,
                                               int M, int N, int K) {
    __shared__ float As[32][72];   // [k][m], pad 8 -> 288B rows (16B aligned)
    __shared__ float Bs[32][72];   // [k][n]
    const int tid = threadIdx.x;
    const int bm = blockIdx.x * 64, bn = blockIdx.y * 64;
    const int r0 = (tid & 15) * 4, c0 = (tid >> 4) * 4;

    // A-load mapping: m = tid/4 (0..63), kq = (tid%4)*8
    const int am = tid >> 2, akq = (tid & 3) * 8;
    // B-load mapping: k = tid/8 (0..31), nq = (tid%8)*8
    const int bk = tid >> 3, bnq = (tid & 7) * 8;

    float acc[4][4] = {};

    for (int k0 = 0; k0 < K; k0 += 32) {
        // A tile 64m x 32k, float4 global loads along k, transpose into As[k][m]
        {
            const float* Ap = A + (size_t)(bm + am) * K + k0 + akq;
            float4 a0 = *(const float4*)Ap;
            float4 a1 = *(const float4*)(Ap + 4);
            As[akq + 0][am] = a0.x; As[akq + 1][am] = a0.y;
            As[akq + 2][am] = a0.z; As[akq + 3][am] = a0.w;
            As[akq + 4][am] = a1.x; As[akq + 5][am] = a1.y;
            As[akq + 6][am] = a1.z; As[akq + 7][am] = a1.w;
        }
        // B tile 32k x 64n, float4 direct
        {
            const float* Wp = W + (size_t)(k0 + bk) * N + bn + bnq;
            float4 b0 = *(const float4*)Wp;
            float4 b1 = *(const float4*)(Wp + 4);
            *(float4*)&Bs[bk][bnq]     = b0;
            *(float4*)&Bs[bk][bnq + 4] = b1;
        }
        __syncthreads();
#pragma unroll
        for (int ks = 0; ks < 32; ks++) {
            float4 av = *(const float4*)&As[ks][r0];
            float4 bv = *(const float4*)&Bs[ks][c0];
            acc[0][0] += av.x * bv.x; acc[0][1] += av.x * bv.y; acc[0][2] += av.x * bv.z; acc[0][3] += av.x * bv.w;
            acc[1][0] += av.y * bv.x; acc[1][1] += av.y * bv.y; acc[1][2] += av.y * bv.z; acc[1][3] += av.y * bv.w;
            acc[2][0] += av.z * bv.x; acc[2][1] += av.z * bv.y; acc[2][2] += av.z * bv.z; acc[2][3] += av.z * bv.w;
            acc[3][0] += av.w * bv.x; acc[3][1] += av.w * bv.y; acc[3][2] += av.w * bv.z; acc[3][3] += av.w * bv.w;
        }
        __syncthreads();
    }

    float4 bb = *(const float4*)(bias + bn + c0);
    const float* bbp = (const float*)&bb;
#pragma unroll
    for (int i = 0; i < 4; i++) {
        float4 v;
        float* vv = (float*)&v;
#pragma unroll
        for (int j = 0; j < 4; j++) {
            float x = acc[i][j] + bbp[j];
            if (ACT == 1) x = fmaxf(x, 0.0f);
            if (ACT == 2) x = (x > 0.0f) ? x : 0.2f * x;
            vv[j] = x;
        }
        *(float4*)(C + (size_t)(bm + r0 + i) * N + bn + c0) = v;
    }
}

// ---- GEMM v2 (scalar; used only for fc4 N=12) ----
template <int ACT>
__global__ void __launch_bounds__(256) gemm_v2(const float* __restrict__ A,
                                               const float* __restrict__ W,
                                               const float* __restrict__ bias,
                                               float* __restrict__ C,
                                               int M, int N, int K) {
    __shared__ float Asm[64][17];
    __shared__ float Bsm[16][68];
    const int tid = threadIdx.x;
    const int bm = blockIdx.x * 64, bn = blockIdx.y * 64;
    const int r0 = (tid & 15) * 4, c0 = (tid >> 4) * 4;
    float acc[4][4] = {};
    for (int k0 = 0; k0 < K; k0 += 16) {
#pragma unroll
        for (int p = 0; p < 4; p++) {
            int i = p * 256 + tid;
            int m = i & 63, k = i >> 6;
            Asm[m][k] = (k0 + k < K) ? A[(size_t)(bm + m) * K + (k0 + k)] : 0.0f;
        }
#pragma unroll
        for (int p = 0; p < 4; p++) {
            int i = p * 256 + tid;
            int n = i & 63, k = i >> 6;
            Bsm[k][n] = ((k0 + k < K) && (bn + n < N)) ? W[(size_t)(k0 + k) * N + (bn + n)] : 0.0f;
        }
        __syncthreads();
#pragma unroll
        for (int k = 0; k < 16; k++) {
            float a0 = Asm[r0 + 0][k], a1 = Asm[r0 + 1][k];
            float a2 = Asm[r0 + 2][k], a3 = Asm[r0 + 3][k];
            float b0 = Bsm[k][c0 + 0], b1 = Bsm[k][c0 + 1];
            float b2 = Bsm[k][c0 + 2], b3 = Bsm[k][c0 + 3];
            acc[0][0] += a0 * b0; acc[0][1] += a0 * b1; acc[0][2] += a0 * b2; acc[0][3] += a0 * b3;
            acc[1][0] += a1 * b0; acc[1][1] += a1 * b1; acc[1][2] += a1 * b2; acc[1][3] += a1 * b3;
            acc[2][0] += a2 * b0; acc[2][1] += a2 * b1; acc[2][2] += a2 * b2; acc[2][3] += a2 * b3;
            acc[3][0] += a3 * b0; acc[3][1] += a3 * b1; acc[3][2] += a3 * b2; acc[3][3] += a3 * b3;
        }
        __syncthreads();
    }
#pragma unroll
    for (int i = 0; i < 4; i++) {
        int row = bm + r0 + i;
        if (row >= M) continue;
#pragma unroll
        for (int j = 0; j < 4; j++) {
            int col = bn + c0 + j;
            if (col < N) {
                float v = acc[i][j] + bias[col];
                if (ACT == 1) v = fmaxf(v, 0.0f);
                if (ACT == 2) v = (v > 0.0f) ? v : 0.2f * v;
                C[(size_t)row * N + col] = v;
            }
        }
    }
}

// ---- pooling / concat ----
__global__ void __launch_bounds__(256) k_maxk() {
    int idx = blockIdx.x * 256 + threadIdx.x;
    int c = idx & 255;
    size_t r = (size_t)(idx >> 8);
    float m = -FLT_MAX;
    for (int k = 0; k < K_; k++)
        m = fmaxf(m, d_a3[(r * K_ + k) * 256 + c]);
    d_ft[idx] = m;
}

__global__ void __launch_bounds__(256) k_gf() {
    int idx = blockIdx.x * 256 + threadIdx.x;
    int c = idx & 255, b = idx >> 8;
    float m = -FLT_MAX;
    for (int s = 0; s < S_; s++)
        m = fmaxf(m, d_ft[((size_t)b * S_ + s) * 256 + c]);
    d_gfv[idx] = m;
}

__global__ void __launch_bounds__(256) k_cat() {
    size_t idx = (size_t)blockIdx.x * 256 + threadIdx.x;
    int c = (int)(idx & 511);
    size_t r = idx >> 9;
    int b = (int)(r >> 9);
    d_ft2[idx] = (c < 256) ? d_ft[r * 256 + c] : d_gfv[b * 256 + (c - 256)];
}

// ---- final: sym + Morton (x * rcp.rn(den)) + stable reorder ----
__global__ void __launch_bounds__(512) k_final(float* __restrict__ out) {
    const int b = blockIdx.x, tid = threadIdx.x;
    __shared__ float red[512];
    __shared__ float mn3[3], mx3[3];
    __shared__ unsigned long long cod[512];

    const float* cp = d_new_xyz + ((size_t)b * S_ + tid) * 3;
    float p[3] = {cp[0], cp[1], cp[2]};

    for (int ax = 0; ax < 3; ax++) {
        red[tid] = p[ax];
        __syncthreads();
        for (int s = 256; s > 0; s >>= 1) {
            if (tid < s) red[tid] = fminf(red[tid], red[tid + s]);
            __syncthreads();
        }
        if (tid == 0) mn3[ax] = red[0];
        __syncthreads();
        red[tid] = p[ax];
        __syncthreads();
        for (int s = 256; s > 0; s >>= 1) {
            if (tid < s) red[tid] = fmaxf(red[tid], red[tid + s]);
            __syncthreads();
        }
        if (tid == 0) mx3[ax] = red[0];
        __syncthreads();
    }

    unsigned long long code = 0;
#pragma unroll
    for (int ax = 0; ax < 3; ax++) {
        float num = __fsub_rn(p[ax], mn3[ax]);
        float den = __fadd_rn(__fsub_rn(mx3[ax], mn3[ax]), 1e-8f);
        float nrm = div_rcp_rn(num, den);
        long long q = (long long)nrm;
        q *= 65535LL;
        if (q < 0) q = 0;
        if (q > 65535) q = 65535;
        unsigned long long m = (unsigned long long)q;
        m = (m | (m << 8)) & 0x00FF00FFull;
        m = (m | (m << 4)) & 0x0F0F0F0Full;
        m = (m | (m << 2)) & 0x33333333ull;
        m = (m | (m << 1)) & 0x55555555ull;
        code |= m << (2 - ax);
    }
    cod[tid] = code;
    __syncthreads();

    int rank = 0;
    for (int j = 0; j < 512; j++) {
        unsigned long long cj = cod[j];
        rank += (cj < code || (cj == code && j < tid)) ? 1 : 0;
    }

    const float* rr = d_y4 + ((size_t)b * S_ + tid) * 12;
    float s0 = p[0] * rr[0] + p[1] * rr[3] + p[2] * rr[6] + rr[9];
    float s1 = p[0] * rr[1] + p[1] * rr[4] + p[2] * rr[7] + rr[10];
    float s2 = p[0] * rr[2] + p[1] * rr[5] + p[2] * rr[8] + rr[11];

    float* o = out + ((size_t)b * (2 * S_) + 2 * (size_t)rank) * 3;
    o[0] = p[0]; o[1] = p[1]; o[2] = p[2];
    o[3] = s0;   o[4] = s1;   o[5] = s2;
}

// ---- launcher ----
extern "C" void kernel_launch(void* const* d_in, const int* in_sizes, int n_in,
                              void* d_out, int out_size) {
    (void)out_size;
    int map[15];
    {
        const int want[15] = {393216, 384, 64, 8192, 128, 32768, 256,
                              262144, 512, 131072, 256, 32768, 128, 1536, 12};
        bool dict_order = (n_in == 15);
        if (dict_order)
            for (int i = 0; i < 15; i++)
                if (in_sizes[i] != want[i]) { dict_order = false; break; }
        if (dict_order) {
            for (int i = 0; i < 15; i++) map[i] = i;
        } else {
            int used[64] = {0};
            for (int lo = 0; lo < 15; lo++) {
                map[lo] = 0;
                for (int i = 0; i < n_in && i < 64; i++)
                    if (!used[i] && in_sizes[i] == want[lo]) { map[lo] = i; used[i] = 1; break; }
            }
        }
    }
    const float* pc    = (const float*)d_in[map[0]];
    const float* w_sa1 = (const float*)d_in[map[1]];
    const float* b_sa1 = (const float*)d_in[map[2]];
    const float* w_sa2 = (const float*)d_in[map[3]];
    const float* b_sa2 = (const float*)d_in[map[4]];
    const float* w_sa3 = (const float*)d_in[map[5]];
    const float* b_sa3 = (const float*)d_in[map[6]];
    const float* w1 = (const float*)d_in[map[7]];
    const float* b1 = (const float*)d_in[map[8]];
    const float* w2 = (const float*)d_in[map[9]];
    const float* b2 = (const float*)d_in[map[10]];
    const float* w3 = (const float*)d_in[map[11]];
    const float* b3 = (const float*)d_in[map[12]];
    const float* w4 = (const float*)d_in[map[13]];
    const float* b4 = (const float*)d_in[map[14]];
    float* out = (float*)d_out;

    float *a1, *a2, *a3, *ft2, *y1, *y2, *y3, *y4;
    cudaGetSymbolAddress((void**)&a1,  d_a1);
    cudaGetSymbolAddress((void**)&a2,  d_a2);
    cudaGetSymbolAddress((void**)&a3,  d_a3);
    cudaGetSymbolAddress((void**)&ft2, d_ft2);
    cudaGetSymbolAddress((void**)&y1,  d_y1);
    cudaGetSymbolAddress((void**)&y2,  d_y2);
    cudaGetSymbolAddress((void**)&y3,  d_y3);
    cudaGetSymbolAddress((void**)&y4,  d_y4);

    k_fps<<<B_, 1024>>>(pc);
    k_knn<<<dim3(8, B_), 256>>>(pc);
    k_sa1<<<NPTS / 256, 256>>>(pc, w_sa1, b_sa1);

    gemm_v3<1><<<dim3(NPTS / 64, 2), 256>>>(a1, w_sa2, b_sa2, a2, NPTS, 128, 64);
    gemm_v3<1><<<dim3(NPTS / 64, 4), 256>>>(a2, w_sa3, b_sa3, a3, NPTS, 256, 128);

    k_maxk<<<NROW, 256>>>();
    k_gf<<<B_, 256>>>();
    k_cat<<<NROW * 512 / 256, 256>>>();

    gemm_v3<2><<<dim3(NROW / 64, 8), 256>>>(ft2, w1, b1, y1, NROW, 512, 512);
    gemm_v3<2><<<dim3(NROW / 64, 4), 256>>>(y1, w2, b2, y2, NROW, 256, 512);
    gemm_v3<2><<<dim3(NROW / 64, 2), 256>>>(y2, w3, b3, y3, NROW, 128, 256);
    gemm_v2<0><<<dim3(NROW / 64, 1), 256>>>(y3, w4, b4, y4, NROW, 12, 128);

    k_final<<<B_, 512>>>(out);
}

// round 16
// speedup vs baseline: 1.5221x; 1.0986x over previous
#include <cuda_runtime.h>
#include <cfloat>
#include <cstdint>

#define B_   32
#define N_   4096
#define S_   512
#define K_   16
#define NPTS (B_ * S_ * K_)
#define NROW (B_ * S_)

__device__ __forceinline__ float sqdist3(float dx, float dy, float dz) {
    return __fadd_rn(__fadd_rn(__fmul_rn(dx, dx), __fmul_rn(dy, dy)), __fmul_rn(dz, dz));
}

// XLA-GPU broadcast-divisor lowering: x / den -> x * reciprocal(den)
__device__ __forceinline__ float div_rcp_rn(float a, float b) {
    float r; asm("rcp.rn.f32 %0, %1;" : "=f"(r) : "f"(b)); return __fmul_rn(a, r);
}

// ---- static scratch ----
__device__ float d_new_xyz[NROW * 3];
__device__ int   d_knn[NROW * K_];
__device__ float d_a1[(size_t)NPTS * 64];
__device__ float d_a2[(size_t)NPTS * 128];
__device__ float d_a3[(size_t)NPTS * 256];
__device__ float d_ft[(size_t)NROW * 256];
__device__ float d_gfv[B_ * 256];
__device__ float d_ft2[(size_t)NROW * 512];
__device__ float d_y1[(size_t)NROW * 512];
__device__ float d_y2[(size_t)NROW * 256];
__device__ float d_y3[(size_t)NROW * 128];
__device__ float d_y4[(size_t)NROW * 12];

// ---- 1. FPS ----
__global__ void __launch_bounds__(1024, 1) k_fps(const float* __restrict__ xyz) {
    const int b = blockIdx.x, tid = threadIdx.x;
    const float* base = xyz + (size_t)b * N_ * 3;
    float px[4], py[4], pz[4], dd[4];
#pragma unroll
    for (int j = 0; j < 4; j++) {
        int i = tid + j * 1024;
        px[j] = base[i * 3 + 0]; py[j] = base[i * 3 + 1]; pz[j] = base[i * 3 + 2];
        dd[j] = 1e10f;
    }
    __shared__ float s_c[3];
    __shared__ float s_v[32];
    __shared__ int   s_i[32];
    __shared__ int   s_far;
    int far = 0;
    for (int t = 0; t < S_; t++) {
        if (tid == (far & 1023)) {
            int j = far >> 10;
            s_c[0] = px[j]; s_c[1] = py[j]; s_c[2] = pz[j];
        }
        __syncthreads();
        float cx = s_c[0], cy = s_c[1], cz = s_c[2];
        if (tid == 0) {
            float* o = d_new_xyz + ((size_t)b * S_ + t) * 3;
            o[0] = cx; o[1] = cy; o[2] = cz;
        }
        float bv = -1.0f; int bi = 0;
#pragma unroll
        for (int j = 0; j < 4; j++) {
            float d  = sqdist3(px[j] - cx, py[j] - cy, pz[j] - cz);
            float nd = fminf(dd[j], d);
            dd[j] = nd;
            if (nd > bv) { bv = nd; bi = tid + j * 1024; }
        }
#pragma unroll
        for (int o = 16; o > 0; o >>= 1) {
            float ov = __shfl_down_sync(0xffffffffu, bv, o);
            int   oi = __shfl_down_sync(0xffffffffu, bi, o);
            if (ov > bv || (ov == bv && oi < bi)) { bv = ov; bi = oi; }
        }
        if ((tid & 31) == 0) { s_v[tid >> 5] = bv; s_i[tid >> 5] = bi; }
        __syncthreads();
        if (tid < 32) {
            bv = s_v[tid]; bi = s_i[tid];
#pragma unroll
            for (int o = 16; o > 0; o >>= 1) {
                float ov = __shfl_down_sync(0xffffffffu, bv, o);
                int   oi = __shfl_down_sync(0xffffffffu, bi, o);
                if (ov > bv || (ov == bv && oi < bi)) { bv = ov; bi = oi; }
            }
            if (tid == 0) s_far = bi;
        }
        __syncthreads();
        far = s_far;
    }
}

// ---- 2. KNN ----
__global__ void __launch_bounds__(256) k_knn(const float* __restrict__ xyz) {
    const int b = blockIdx.y, c0 = blockIdx.x * 64, tid = threadIdx.x;
    const float* base = xyz + (size_t)b * N_ * 3;
    float px[16], py[16], pz[16];
#pragma unroll
    for (int j = 0; j < 16; j++) {
        int i = tid + j * 256;
        px[j] = base[i * 3 + 0]; py[j] = base[i * 3 + 1]; pz[j] = base[i * 3 + 2];
    }
    __shared__ float s_v[8];
    __shared__ int   s_i[8];
    __shared__ int   s_sel;
    for (int s = 0; s < 64; s++) {
        int sc = c0 + s;
        const float* c = d_new_xyz + ((size_t)b * S_ + sc) * 3;
        float cx = c[0], cy = c[1], cz = c[2];
        float d[16];
#pragma unroll
        for (int j = 0; j < 16; j++)
            d[j] = sqdist3(px[j] - cx, py[j] - cy, pz[j] - cz);
        for (int r = 0; r < K_; r++) {
            float bv = FLT_MAX; int bi = 0x7fffffff;
#pragma unroll
            for (int j = 0; j < 16; j++)
                if (d[j] < bv) { bv = d[j]; bi = tid + j * 256; }
#pragma unroll
            for (int o = 16; o > 0; o >>= 1) {
                float ov = __shfl_down_sync(0xffffffffu, bv, o);
                int   oi = __shfl_down_sync(0xffffffffu, bi, o);
                if (ov < bv || (ov == bv && oi < bi)) { bv = ov; bi = oi; }
            }
            if ((tid & 31) == 0) { s_v[tid >> 5] = bv; s_i[tid >> 5] = bi; }
            __syncthreads();
            if (tid == 0) {
                float mv = s_v[0]; int mi = s_i[0];
#pragma unroll
                for (int w = 1; w < 8; w++)
                    if (s_v[w] < mv || (s_v[w] == mv && s_i[w] < mi)) { mv = s_v[w]; mi = s_i[w]; }
                d_knn[((size_t)b * S_ + sc) * K_ + r] = mi;
                s_sel = mi;
            }
            __syncthreads();
            int sel = s_sel;
#pragma unroll
            for (int j = 0; j < 16; j++)
                if (sel == tid + j * 256) d[j] = FLT_MAX;
        }
    }
}

// ---- 3. fused gather + sa1 (K=6 -> 64, relu) ----
__global__ void __launch_bounds__(256) k_sa1(const float* __restrict__ pc,
                                             const float* __restrict__ w,
                                             const float* __restrict__ bias) {
    __shared__ float ws[6][64];
    __shared__ float bs[64];
    int tid = threadIdx.x;
    if (tid < 64) bs[tid] = bias[tid];
#pragma unroll
    for (int i = tid; i < 384; i += 256) ws[i >> 6][i & 63] = w[i];
    __syncthreads();

    int idx = blockIdx.x * 256 + tid;
    int r = idx >> 4, b = r >> 9;
    int gi = d_knn[idx];
    const float* p = pc + ((size_t)b * N_ + gi) * 3;
    const float* c = d_new_xyz + (size_t)r * 3;
    float gx = p[0], gy = p[1], gz = p[2];
    float f[6] = {gx - c[0], gy - c[1], gz - c[2], gx, gy, gz};

    float* o = d_a1 + (size_t)idx * 64;
#pragma unroll
    for (int n4 = 0; n4 < 16; n4++) {
        float4 v;
        float* vv = (float*)&v;
#pragma unroll
        for (int q = 0; q < 4; q++) {
            int n = n4 * 4 + q;
            float acc = bs[n];
#pragma unroll
            for (int j = 0; j < 6; j++) acc += f[j] * ws[j][n];
            vv[q] = fmaxf(acc, 0.0f);
        }
        *(float4*)(o + n4 * 4) = v;
    }
}

// ---- GEMM v4: 128x128 tile, 256 thr, 8x8 split-fragment microtile ----
// requires M%128==0, N%128==0, K%16==0.
template <int ACT>
__global__ void __launch_bounds__(256) gemm_v4(const float* __restrict__ A,
                                               const float* __restrict__ W,
                                               const float* __restrict__ bias,
                                               float* __restrict__ C,
                                               int M, int N, int K) {
    __shared__ float As[16][132];   // [k][m]
    __shared__ float Bs[16][132];   // [k][n]
    const int tid = threadIdx.x;
    const int bm = blockIdx.x * 128, bn = blockIdx.y * 128;
    const int rx = (tid & 15) * 4;      // row fragment base (plus +64 half)
    const int cx = (tid >> 4) * 4;      // col fragment base (plus +64 half)

    // A-load: row am = tid/2, k-quad akq = (tid%2)*8
    const int am = tid >> 1, akq = (tid & 1) * 8;
    // B-load: k = tid/16, n-quad bnq = (tid%16)*8
    const int bk = tid >> 4, bnq = (tid & 15) * 8;

    float acc[8][8] = {};
    float ar[8], br[8];

    for (int k0 = 0; k0 < K; k0 += 16) {
        {
            const float* Ap = A + (size_t)(bm + am) * K + k0 + akq;
            float4 a0 = *(const float4*)Ap;
            float4 a1 = *(const float4*)(Ap + 4);
            As[akq + 0][am] = a0.x; As[akq + 1][am] = a0.y;
            As[akq + 2][am] = a0.z; As[akq + 3][am] = a0.w;
            As[akq + 4][am] = a1.x; As[akq + 5][am] = a1.y;
            As[akq + 6][am] = a1.z; As[akq + 7][am] = a1.w;
        }
        {
            const float* Wp = W + (size_t)(k0 + bk) * N + bn + bnq;
            *(float4*)&Bs[bk][bnq]     = *(const float4*)Wp;
            *(float4*)&Bs[bk][bnq + 4] = *(const float4*)(Wp + 4);
        }
        __syncthreads();
#pragma unroll
        for (int ks = 0; ks < 16; ks++) {
            *(float4*)&ar[0] = *(const float4*)&As[ks][rx];
            *(float4*)&ar[4] = *(const float4*)&As[ks][64 + rx];
            *(float4*)&br[0] = *(const float4*)&Bs[ks][cx];
            *(float4*)&br[4] = *(const float4*)&Bs[ks][64 + cx];
#pragma unroll
            for (int i = 0; i < 8; i++)
#pragma unroll
                for (int j = 0; j < 8; j++)
                    acc[i][j] += ar[i] * br[j];
        }
        __syncthreads();
    }

    float bb[8];
    *(float4*)&bb[0] = *(const float4*)(bias + bn + cx);
    *(float4*)&bb[4] = *(const float4*)(bias + bn + 64 + cx);
#pragma unroll
    for (int i = 0; i < 8; i++) {
        int row = bm + ((i < 4) ? (rx + i) : (64 + rx + i - 4));
        float4 v0, v1;
        float* p0 = (float*)&v0;
        float* p1 = (float*)&v1;
#pragma unroll
        for (int j = 0; j < 4; j++) {
            float x = acc[i][j] + bb[j];
            if (ACT == 1) x = fmaxf(x, 0.0f);
            if (ACT == 2) x = (x > 0.0f) ? x : 0.2f * x;
            p0[j] = x;
            float y = acc[i][j + 4] + bb[j + 4];
            if (ACT == 1) y = fmaxf(y, 0.0f);
            if (ACT == 2) y = (y > 0.0f) ? y : 0.2f * y;
            p1[j] = y;
        }
        *(float4*)(C + (size_t)row * N + bn + cx)      = v0;
        *(float4*)(C + (size_t)row * N + bn + 64 + cx) = v1;
    }
}

// ---- GEMM v2 (scalar; used only for fc4 N=12) ----
template <int ACT>
__global__ void __launch_bounds__(256) gemm_v2(const float* __restrict__ A,
                                               const float* __restrict__ W,
                                               const float* __restrict__ bias,
                                               float* __restrict__ C,
                                               int M, int N, int K) {
    __shared__ float Asm[64][17];
    __shared__ float Bsm[16][68];
    const int tid = threadIdx.x;
    const int bm = blockIdx.x * 64, bn = blockIdx.y * 64;
    const int r0 = (tid & 15) * 4, c0 = (tid >> 4) * 4;
    float acc[4][4] = {};
    for (int k0 = 0; k0 < K; k0 += 16) {
#pragma unroll
        for (int p = 0; p < 4; p++) {
            int i = p * 256 + tid;
            int m = i & 63, k = i >> 6;
            Asm[m][k] = (k0 + k < K) ? A[(size_t)(bm + m) * K + (k0 + k)] : 0.0f;
        }
#pragma unroll
        for (int p = 0; p < 4; p++) {
            int i = p * 256 + tid;
            int n = i & 63, k = i >> 6;
            Bsm[k][n] = ((k0 + k < K) && (bn + n < N)) ? W[(size_t)(k0 + k) * N + (bn + n)] : 0.0f;
        }
        __syncthreads();
#pragma unroll
        for (int k = 0; k < 16; k++) {
            float a0 = Asm[r0 + 0][k], a1 = Asm[r0 + 1][k];
            float a2 = Asm[r0 + 2][k], a3 = Asm[r0 + 3][k];
            float b0 = Bsm[k][c0 + 0], b1 = Bsm[k][c0 + 1];
            float b2 = Bsm[k][c0 + 2], b3 = Bsm[k][c0 + 3];
            acc[0][0] += a0 * b0; acc[0][1] += a0 * b1; acc[0][2] += a0 * b2; acc[0][3] += a0 * b3;
            acc[1][0] += a1 * b0; acc[1][1] += a1 * b1; acc[1][2] += a1 * b2; acc[1][3] += a1 * b3;
            acc[2][0] += a2 * b0; acc[2][1] += a2 * b1; acc[2][2] += a2 * b2; acc[2][3] += a2 * b3;
            acc[3][0] += a3 * b0; acc[3][1] += a3 * b1; acc[3][2] += a3 * b2; acc[3][3] += a3 * b3;
        }
        __syncthreads();
    }
#pragma unroll
    for (int i = 0; i < 4; i++) {
        int row = bm + r0 + i;
        if (row >= M) continue;
#pragma unroll
        for (int j = 0; j < 4; j++) {
            int col = bn + c0 + j;
            if (col < N) {
                float v = acc[i][j] + bias[col];
                if (ACT == 1) v = fmaxf(v, 0.0f);
                if (ACT == 2) v = (v > 0.0f) ? v : 0.2f * v;
                C[(size_t)row * N + col] = v;
            }
        }
    }
}

// ---- pooling / concat ----
__global__ void __launch_bounds__(256) k_maxk() {
    int idx = blockIdx.x * 256 + threadIdx.x;
    int c = idx & 255;
    size_t r = (size_t)(idx >> 8);
    float m = -FLT_MAX;
    for (int k = 0; k < K_; k++)
        m = fmaxf(m, d_a3[(r * K_ + k) * 256 + c]);
    d_ft[idx] = m;
}

__global__ void __launch_bounds__(256) k_gf() {
    int idx = blockIdx.x * 256 + threadIdx.x;
    int c = idx & 255, b = idx >> 8;
    float m = -FLT_MAX;
    for (int s = 0; s < S_; s++)
        m = fmaxf(m, d_ft[((size_t)b * S_ + s) * 256 + c]);
    d_gfv[idx] = m;
}

__global__ void __launch_bounds__(256) k_cat() {
    size_t idx = (size_t)blockIdx.x * 256 + threadIdx.x;
    int c = (int)(idx & 511);
    size_t r = idx >> 9;
    int b = (int)(r >> 9);
    d_ft2[idx] = (c < 256) ? d_ft[r * 256 + c] : d_gfv[b * 256 + (c - 256)];
}

// ---- final: sym + Morton (x * rcp.rn(den)) + stable reorder ----
__global__ void __launch_bounds__(512) k_final(float* __restrict__ out) {
    const int b = blockIdx.x, tid = threadIdx.x;
    __shared__ float red[512];
    __shared__ float mn3[3], mx3[3];
    __shared__ unsigned long long cod[512];

    const float* cp = d_new_xyz + ((size_t)b * S_ + tid) * 3;
    float p[3] = {cp[0], cp[1], cp[2]};

    for (int ax = 0; ax < 3; ax++) {
        red[tid] = p[ax];
        __syncthreads();
        for (int s = 256; s > 0; s >>= 1) {
            if (tid < s) red[tid] = fminf(red[tid], red[tid + s]);
            __syncthreads();
        }
        if (tid == 0) mn3[ax] = red[0];
        __syncthreads();
        red[tid] = p[ax];
        __syncthreads();
        for (int s = 256; s > 0; s >>= 1) {
            if (tid < s) red[tid] = fmaxf(red[tid], red[tid + s]);
            __syncthreads();
        }
        if (tid == 0) mx3[ax] = red[0];
        __syncthreads();
    }

    unsigned long long code = 0;
#pragma unroll
    for (int ax = 0; ax < 3; ax++) {
        float num = __fsub_rn(p[ax], mn3[ax]);
        float den = __fadd_rn(__fsub_rn(mx3[ax], mn3[ax]), 1e-8f);
        float nrm = div_rcp_rn(num, den);
        long long q = (long long)nrm;
        q *= 65535LL;
        if (q < 0) q = 0;
        if (q > 65535) q = 65535;
        unsigned long long m = (unsigned long long)q;
        m = (m | (m << 8)) & 0x00FF00FFull;
        m = (m | (m << 4)) & 0x0F0F0F0Full;
        m = (m | (m << 2)) & 0x33333333ull;
        m = (m | (m << 1)) & 0x55555555ull;
        code |= m << (2 - ax);
    }
    cod[tid] = code;
    __syncthreads();

    int rank = 0;
    for (int j = 0; j < 512; j++) {
        unsigned long long cj = cod[j];
        rank += (cj < code || (cj == code && j < tid)) ? 1 : 0;
    }

    const float* rr = d_y4 + ((size_t)b * S_ + tid) * 12;
    float s0 = p[0] * rr[0] + p[1] * rr[3] + p[2] * rr[6] + rr[9];
    float s1 = p[0] * rr[1] + p[1] * rr[4] + p[2] * rr[7] + rr[10];
    float s2 = p[0] * rr[2] + p[1] * rr[5] + p[2] * rr[8] + rr[11];

    float* o = out + ((size_t)b * (2 * S_) + 2 * (size_t)rank) * 3;
    o[0] = p[0]; o[1] = p[1]; o[2] = p[2];
    o[3] = s0;   o[4] = s1;   o[5] = s2;
}

// ---- launcher ----
extern "C" void kernel_launch(void* const* d_in, const int* in_sizes, int n_in,
                              void* d_out, int out_size) {
    (void)out_size;
    int map[15];
    {
        const int want[15] = {393216, 384, 64, 8192, 128, 32768, 256,
                              262144, 512, 131072, 256, 32768, 128, 1536, 12};
        bool dict_order = (n_in == 15);
        if (dict_order)
            for (int i = 0; i < 15; i++)
                if (in_sizes[i] != want[i]) { dict_order = false; break; }
        if (dict_order) {
            for (int i = 0; i < 15; i++) map[i] = i;
        } else {
            int used[64] = {0};
            for (int lo = 0; lo < 15; lo++) {
                map[lo] = 0;
                for (int i = 0; i < n_in && i < 64; i++)
                    if (!used[i] && in_sizes[i] == want[lo]) { map[lo] = i; used[i] = 1; break; }
            }
        }
    }
    const float* pc    = (const float*)d_in[map[0]];
    const float* w_sa1 = (const float*)d_in[map[1]];
    const float* b_sa1 = (const float*)d_in[map[2]];
    const float* w_sa2 = (const float*)d_in[map[3]];
    const float* b_sa2 = (const float*)d_in[map[4]];
    const float* w_sa3 = (const float*)d_in[map[5]];
    const float* b_sa3 = (const float*)d_in[map[6]];
    const float* w1 = (const float*)d_in[map[7]];
    const float* b1 = (const float*)d_in[map[8]];
    const float* w2 = (const float*)d_in[map[9]];
    const float* b2 = (const float*)d_in[map[10]];
    const float* w3 = (const float*)d_in[map[11]];
    const float* b3 = (const float*)d_in[map[12]];
    const float* w4 = (const float*)d_in[map[13]];
    const float* b4 = (const float*)d_in[map[14]];
    float* out = (float*)d_out;

    float *a1, *a2, *a3, *ft2, *y1, *y2, *y3, *y4;
    cudaGetSymbolAddress((void**)&a1,  d_a1);
    cudaGetSymbolAddress((void**)&a2,  d_a2);
    cudaGetSymbolAddress((void**)&a3,  d_a3);
    cudaGetSymbolAddress((void**)&ft2, d_ft2);
    cudaGetSymbolAddress((void**)&y1,  d_y1);
    cudaGetSymbolAddress((void**)&y2,  d_y2);
    cudaGetSymbolAddress((void**)&y3,  d_y3);
    cudaGetSymbolAddress((void**)&y4,  d_y4);

    k_fps<<<B_, 1024>>>(pc);
    k_knn<<<dim3(8, B_), 256>>>(pc);
    k_sa1<<<NPTS / 256, 256>>>(pc, w_sa1, b_sa1);

    gemm_v4<1><<<dim3(NPTS / 128, 1), 256>>>(a1, w_sa2, b_sa2, a2, NPTS, 128, 64);
    gemm_v4<1><<<dim3(NPTS / 128, 2), 256>>>(a2, w_sa3, b_sa3, a3, NPTS, 256, 128);

    k_maxk<<<NROW, 256>>>();
    k_gf<<<B_, 256>>>();
    k_cat<<<NROW * 512 / 256, 256>>>();

    gemm_v4<2><<<dim3(NROW / 128, 4), 256>>>(ft2, w1, b1, y1, NROW, 512, 512);
    gemm_v4<2><<<dim3(NROW / 128, 2), 256>>>(y1, w2, b2, y2, NROW, 256, 512);
    gemm_v4<2><<<dim3(NROW / 128, 1), 256>>>(y2, w3, b3, y3, NROW, 128, 256);
    gemm_v2<0><<<dim3(NROW / 64, 1), 256>>>(y3, w4, b4, y4, NROW, 12, 128);

    k_final<<<B_, 512>>>(out);
}

// round 17
// speedup vs baseline: 1.7209x; 1.1306x over previous
#include <cuda_runtime.h>
#include <cfloat>
#include <cstdint>

#define B_   32
#define N_   4096
#define S_   512
#define K_   16
#define NPTS (B_ * S_ * K_)
#define NROW (B_ * S_)

__device__ __forceinline__ float sqdist3(float dx, float dy, float dz) {
    return __fadd_rn(__fadd_rn(__fmul_rn(dx, dx), __fmul_rn(dy, dy)), __fmul_rn(dz, dz));
}

// XLA-GPU broadcast-divisor lowering: x / den -> x * reciprocal(den)
__device__ __forceinline__ float div_rcp_rn(float a, float b) {
    float r; asm("rcp.rn.f32 %0, %1;" : "=f"(r) : "f"(b)); return __fmul_rn(a, r);
}

// ---- static scratch ----
__device__ float d_new_xyz[NROW * 3];
__device__ int   d_knn[NROW * K_];
__device__ float d_a1[(size_t)NPTS * 64];
__device__ float d_a2[(size_t)NPTS * 128];
__device__ float d_ft[(size_t)NROW * 256];
__device__ float d_gfv[B_ * 256];
__device__ float d_y1[(size_t)NROW * 512];
__device__ float d_y2[(size_t)NROW * 256];
__device__ float d_y3[(size_t)NROW * 128];
__device__ float d_y4[(size_t)NROW * 12];

// ---- 1. FPS v2: 512 thr, 8 pts/thread, 1 barrier/iter ----
__global__ void __launch_bounds__(512, 1) k_fps(const float* __restrict__ xyz) {
    const int b = blockIdx.x, tid = threadIdx.x;
    const int w = tid >> 5, lane = tid & 31;
    __shared__ float spx[N_], spy[N_], spz[N_];
    __shared__ float s_v[2][16];
    __shared__ int   s_i[2][16];

    const float* base = xyz + (size_t)b * N_ * 3;
    float px[8], py[8], pz[8], dd[8];
#pragma unroll
    for (int j = 0; j < 8; j++) {
        int i = tid + j * 512;
        float x = base[i * 3 + 0], y = base[i * 3 + 1], z = base[i * 3 + 2];
        px[j] = x; py[j] = y; pz[j] = z;
        spx[i] = x; spy[i] = y; spz[i] = z;
        dd[j] = 1e10f;
    }
    __syncthreads();

    int far = 0;
    float* outb = d_new_xyz + (size_t)b * S_ * 3;
    for (int t = 0; t < S_; t++) {
        float cx = spx[far], cy = spy[far], cz = spz[far];   // broadcast LDS
        if (tid == 0) {
            outb[t * 3 + 0] = cx; outb[t * 3 + 1] = cy; outb[t * 3 + 2] = cz;
        }
        float bv = -1.0f; int bi = 0;
#pragma unroll
        for (int j = 0; j < 8; j++) {
            float d  = sqdist3(px[j] - cx, py[j] - cy, pz[j] - cz);
            float nd = fminf(dd[j], d);
            dd[j] = nd;
            if (nd > bv) { bv = nd; bi = tid + j * 512; }  // ascending idx, strict >
        }
#pragma unroll
        for (int o = 16; o > 0; o >>= 1) {
            float ov = __shfl_down_sync(0xffffffffu, bv, o);
            int   oi = __shfl_down_sync(0xffffffffu, bi, o);
            if (ov > bv || (ov == bv && oi < bi)) { bv = ov; bi = oi; }
        }
        int par = t & 1;
        if (lane == 0) { s_v[par][w] = bv; s_i[par][w] = bi; }
        __syncthreads();
        // all threads scan 16 warp results (broadcast reads)
        float mv = s_v[par][0]; int mi = s_i[par][0];
#pragma unroll
        for (int q = 1; q < 16; q++) {
            float qv = s_v[par][q]; int qi = s_i[par][q];
            if (qv > mv || (qv == mv && qi < mi)) { mv = qv; mi = qi; }
        }
        far = mi;
    }
}

// ---- 2. KNN v2: 2 centers per round-trip, 1 barrier/round ----
// grid (16, B_): block handles 32 centers of one batch, in 16 pairs.
__global__ void __launch_bounds__(256) k_knn(const float* __restrict__ xyz) {
    const int b = blockIdx.y, cbase = blockIdx.x * 32, tid = threadIdx.x;
    const int w = tid >> 5, lane = tid & 31;
    const float* base = xyz + (size_t)b * N_ * 3;
    float px[16], py[16], pz[16];
#pragma unroll
    for (int j = 0; j < 16; j++) {
        int i = tid + j * 256;
        px[j] = base[i * 3 + 0]; py[j] = base[i * 3 + 1]; pz[j] = base[i * 3 + 2];
    }
    __shared__ float s_v[2][2][8];
    __shared__ int   s_i[2][2][8];

    for (int grp = 0; grp < 16; grp++) {
        int sc0 = cbase + grp * 2;
        const float* c0p = d_new_xyz + ((size_t)b * S_ + sc0) * 3;
        float c0x = c0p[0], c0y = c0p[1], c0z = c0p[2];
        float c1x = c0p[3], c1y = c0p[4], c1z = c0p[5];
        float d0[16], d1[16];
#pragma unroll
        for (int j = 0; j < 16; j++) {
            d0[j] = sqdist3(px[j] - c0x, py[j] - c0y, pz[j] - c0z);
            d1[j] = sqdist3(px[j] - c1x, py[j] - c1y, pz[j] - c1z);
        }
        for (int r = 0; r < K_; r++) {
            int par = r & 1;
            float bv0 = FLT_MAX, bv1 = FLT_MAX;
            int   bi0 = 0x7fffffff, bi1 = 0x7fffffff;
#pragma unroll
            for (int j = 0; j < 16; j++) {
                int idx = tid + j * 256;
                if (d0[j] < bv0) { bv0 = d0[j]; bi0 = idx; }
                if (d1[j] < bv1) { bv1 = d1[j]; bi1 = idx; }
            }
#pragma unroll
            for (int o = 16; o > 0; o >>= 1) {
                float ov0 = __shfl_down_sync(0xffffffffu, bv0, o);
                int   oi0 = __shfl_down_sync(0xffffffffu, bi0, o);
                float ov1 = __shfl_down_sync(0xffffffffu, bv1, o);
                int   oi1 = __shfl_down_sync(0xffffffffu, bi1, o);
                if (ov0 < bv0 || (ov0 == bv0 && oi0 < bi0)) { bv0 = ov0; bi0 = oi0; }
                if (ov1 < bv1 || (ov1 == bv1 && oi1 < bi1)) { bv1 = ov1; bi1 = oi1; }
            }
            if (lane == 0) {
                s_v[par][0][w] = bv0; s_i[par][0][w] = bi0;
                s_v[par][1][w] = bv1; s_i[par][1][w] = bi1;
            }
            __syncthreads();
            float m0 = s_v[par][0][0]; int w0 = s_i[par][0][0];
            float m1 = s_v[par][1][0]; int w1 = s_i[par][1][0];
#pragma unroll
            for (int q = 1; q < 8; q++) {
                float q0 = s_v[par][0][q]; int qi0 = s_i[par][0][q];
                float q1 = s_v[par][1][q]; int qi1 = s_i[par][1][q];
                if (q0 < m0 || (q0 == m0 && qi0 < w0)) { m0 = q0; w0 = qi0; }
                if (q1 < m1 || (q1 == m1 && qi1 < w1)) { m1 = q1; w1 = qi1; }
            }
            if (tid == 0) {
                d_knn[((size_t)b * S_ + sc0) * K_ + r]     = w0;
                d_knn[((size_t)b * S_ + sc0 + 1) * K_ + r] = w1;
            }
#pragma unroll
            for (int j = 0; j < 16; j++) {
                int idx = tid + j * 256;
                if (idx == w0) d0[j] = FLT_MAX;
                if (idx == w1) d1[j] = FLT_MAX;
            }
        }
    }
}

// ---- 3. fused gather + sa1 (K=6 -> 64, relu) ----
__global__ void __launch_bounds__(256) k_sa1(const float* __restrict__ pc,
                                             const float* __restrict__ w,
                                             const float* __restrict__ bias) {
    __shared__ float ws[6][64];
    __shared__ float bs[64];
    int tid = threadIdx.x;
    if (tid < 64) bs[tid] = bias[tid];
#pragma unroll
    for (int i = tid; i < 384; i += 256) ws[i >> 6][i & 63] = w[i];
    __syncthreads();

    int idx = blockIdx.x * 256 + tid;
    int r = idx >> 4, b = r >> 9;
    int gi = d_knn[idx];
    const float* p = pc + ((size_t)b * N_ + gi) * 3;
    const float* c = d_new_xyz + (size_t)r * 3;
    float gx = p[0], gy = p[1], gz = p[2];
    float f[6] = {gx - c[0], gy - c[1], gz - c[2], gx, gy, gz};

    float* o = d_a1 + (size_t)idx * 64;
#pragma unroll
    for (int n4 = 0; n4 < 16; n4++) {
        float4 v;
        float* vv = (float*)&v;
#pragma unroll
        for (int q = 0; q < 4; q++) {
            int n = n4 * 4 + q;
            float acc = bs[n];
#pragma unroll
            for (int j = 0; j < 6; j++) acc += f[j] * ws[j][n];
            vv[q] = fmaxf(acc, 0.0f);
        }
        *(float4*)(o + n4 * 4) = v;
    }
}

// ---- GEMM v5: 128x128 tile, A-reg prefetch, optional fused max-over-16-rows
//      epilogue (FUSEMAX) and fused concat A-source (CATA). ----
template <int ACT, int FUSEMAX, int CATA>
__global__ void __launch_bounds__(256, 2) gemm_v5(const float* __restrict__ A,
                                                  const float* __restrict__ W,
                                                  const float* __restrict__ bias,
                                                  float* __restrict__ C,
                                                  int M, int N, int K,
                                                  const float* __restrict__ gfv) {
    __shared__ float As[16][132];
    __shared__ float Bs[16][132];
    const int tid = threadIdx.x;
    const int bm = blockIdx.x * 128, bn = blockIdx.y * 128;
    const int rx = (tid & 15) * 4, cx = (tid >> 4) * 4;
    const int am = tid >> 1, akq = (tid & 1) * 8;
    const int bk = tid >> 4, bnq = (tid & 15) * 8;

    float acc[8][8] = {};
    float ar[8], br[8], pa[8];

    auto loadA = [&](int k0) {
        if (CATA) {
            int kg = k0 + akq;
            int row = bm + am;
            const float* src = (kg < 256) ? (A + (size_t)row * 256 + kg)
                                          : (gfv + (size_t)(row >> 9) * 256 + (kg - 256));
            float4 a0 = *(const float4*)src;
            float4 a1 = *(const float4*)(src + 4);
            pa[0] = a0.x; pa[1] = a0.y; pa[2] = a0.z; pa[3] = a0.w;
            pa[4] = a1.x; pa[5] = a1.y; pa[6] = a1.z; pa[7] = a1.w;
        } else {
            const float* Ap = A + (size_t)(bm + am) * K + k0 + akq;
            float4 a0 = *(const float4*)Ap;
            float4 a1 = *(const float4*)(Ap + 4);
            pa[0] = a0.x; pa[1] = a0.y; pa[2] = a0.z; pa[3] = a0.w;
            pa[4] = a1.x; pa[5] = a1.y; pa[6] = a1.z; pa[7] = a1.w;
        }
    };

    loadA(0);
    for (int k0 = 0; k0 < K; k0 += 16) {
#pragma unroll
        for (int q = 0; q < 8; q++) As[akq + q][am] = pa[q];
        {
            const float* Wp = W + (size_t)(k0 + bk) * N + bn + bnq;
            *(float4*)&Bs[bk][bnq]     = *(const float4*)Wp;
            *(float4*)&Bs[bk][bnq + 4] = *(const float4*)(Wp + 4);
        }
        __syncthreads();
        if (k0 + 16 < K) loadA(k0 + 16);
#pragma unroll
        for (int ks = 0; ks < 16; ks++) {
            *(float4*)&ar[0] = *(const float4*)&As[ks][rx];
            *(float4*)&ar[4] = *(const float4*)&As[ks][64 + rx];
            *(float4*)&br[0] = *(const float4*)&Bs[ks][cx];
            *(float4*)&br[4] = *(const float4*)&Bs[ks][64 + cx];
#pragma unroll
            for (int i = 0; i < 8; i++)
#pragma unroll
                for (int j = 0; j < 8; j++)
                    acc[i][j] += ar[i] * br[j];
        }
        __syncthreads();
    }

    float bb[8];
    *(float4*)&bb[0] = *(const float4*)(bias + bn + cx);
    *(float4*)&bb[4] = *(const float4*)(bias + bn + 64 + cx);

    if (FUSEMAX) {
        // group max over 16 consecutive rows (relu outputs >= 0, int-bit monotone)
        __shared__ int gmax[8][128];
        for (int i = tid; i < 1024; i += 256) ((int*)gmax)[i] = 0;
        __syncthreads();
#pragma unroll
        for (int i = 0; i < 8; i++) {
            int row_in = (i < 4) ? (rx + i) : (64 + rx + i - 4);
            int g = row_in >> 4;
#pragma unroll
            for (int j = 0; j < 8; j++) {
                int col_in = (j < 4) ? (cx + j) : (64 + cx + j - 4);
                float x = fmaxf(acc[i][j] + bb[j], 0.0f);
                atomicMax(&gmax[g][col_in], __float_as_int(x));
            }
        }
        __syncthreads();
        for (int i = tid; i < 1024; i += 256) {
            int g = i >> 7, col = i & 127;
            C[((size_t)(bm >> 4) + g) * N + bn + col] = __int_as_float(gmax[g][col]);
        }
        return;
    }

#pragma unroll
    for (int i = 0; i < 8; i++) {
        int row = bm + ((i < 4) ? (rx + i) : (64 + rx + i - 4));
        float4 v0, v1;
        float* p0 = (float*)&v0;
        float* p1 = (float*)&v1;
#pragma unroll
        for (int j = 0; j < 4; j++) {
            float x = acc[i][j] + bb[j];
            if (ACT == 1) x = fmaxf(x, 0.0f);
            if (ACT == 2) x = (x > 0.0f) ? x : 0.2f * x;
            p0[j] = x;
            float y = acc[i][j + 4] + bb[j + 4];
            if (ACT == 1) y = fmaxf(y, 0.0f);
            if (ACT == 2) y = (y > 0.0f) ? y : 0.2f * y;
            p1[j] = y;
        }
        *(float4*)(C + (size_t)row * N + bn + cx)      = v0;
        *(float4*)(C + (size_t)row * N + bn + 64 + cx) = v1;
    }
}

// ---- GEMM v2 (scalar; fc4 N=12 only) ----
template <int ACT>
__global__ void __launch_bounds__(256) gemm_v2(const float* __restrict__ A,
                                               const float* __restrict__ W,
                                               const float* __restrict__ bias,
                                               float* __restrict__ C,
                                               int M, int N, int K) {
    __shared__ float Asm[64][17];
    __shared__ float Bsm[16][68];
    const int tid = threadIdx.x;
    const int bm = blockIdx.x * 64, bn = blockIdx.y * 64;
    const int r0 = (tid & 15) * 4, c0 = (tid >> 4) * 4;
    float acc[4][4] = {};
    for (int k0 = 0; k0 < K; k0 += 16) {
#pragma unroll
        for (int p = 0; p < 4; p++) {
            int i = p * 256 + tid;
            int m = i & 63, k = i >> 6;
            Asm[m][k] = (k0 + k < K) ? A[(size_t)(bm + m) * K + (k0 + k)] : 0.0f;
        }
#pragma unroll
        for (int p = 0; p < 4; p++) {
            int i = p * 256 + tid;
            int n = i & 63, k = i >> 6;
            Bsm[k][n] = ((k0 + k < K) && (bn + n < N)) ? W[(size_t)(k0 + k) * N + (bn + n)] : 0.0f;
        }
        __syncthreads();
#pragma unroll
        for (int k = 0; k < 16; k++) {
            float a0 = Asm[r0 + 0][k], a1 = Asm[r0 + 1][k];
            float a2 = Asm[r0 + 2][k], a3 = Asm[r0 + 3][k];
            float b0 = Bsm[k][c0 + 0], b1 = Bsm[k][c0 + 1];
            float b2 = Bsm[k][c0 + 2], b3 = Bsm[k][c0 + 3];
            acc[0][0] += a0 * b0; acc[0][1] += a0 * b1; acc[0][2] += a0 * b2; acc[0][3] += a0 * b3;
            acc[1][0] += a1 * b0; acc[1][1] += a1 * b1; acc[1][2] += a1 * b2; acc[1][3] += a1 * b3;
            acc[2][0] += a2 * b0; acc[2][1] += a2 * b1; acc[2][2] += a2 * b2; acc[2][3] += a2 * b3;
            acc[3][0] += a3 * b0; acc[3][1] += a3 * b1; acc[3][2] += a3 * b2; acc[3][3] += a3 * b3;
        }
        __syncthreads();
    }
#pragma unroll
    for (int i = 0; i < 4; i++) {
        int row = bm + r0 + i;
        if (row >= M) continue;
#pragma unroll
        for (int j = 0; j < 4; j++) {
            int col = bn + c0 + j;
            if (col < N) {
                float v = acc[i][j] + bias[col];
                if (ACT == 1) v = fmaxf(v, 0.0f);
                if (ACT == 2) v = (v > 0.0f) ? v : 0.2f * v;
                C[(size_t)row * N + col] = v;
            }
        }
    }
}

// ---- global feature (max over S) ----
__global__ void __launch_bounds__(256) k_gf() {
    int idx = blockIdx.x * 256 + threadIdx.x;
    int c = idx & 255, b = idx >> 8;
    float m = -FLT_MAX;
    for (int s = 0; s < S_; s++)
        m = fmaxf(m, d_ft[((size_t)b * S_ + s) * 256 + c]);
    d_gfv[idx] = m;
}

// ---- final: sym + Morton (x * rcp.rn(den)) + stable reorder ----
__global__ void __launch_bounds__(512) k_final(float* __restrict__ out) {
    const int b = blockIdx.x, tid = threadIdx.x;
    __shared__ float red[512];
    __shared__ float mn3[3], mx3[3];
    __shared__ unsigned long long cod[512];

    const float* cp = d_new_xyz + ((size_t)b * S_ + tid) * 3;
    float p[3] = {cp[0], cp[1], cp[2]};

    for (int ax = 0; ax < 3; ax++) {
        red[tid] = p[ax];
        __syncthreads();
        for (int s = 256; s > 0; s >>= 1) {
            if (tid < s) red[tid] = fminf(red[tid], red[tid + s]);
            __syncthreads();
        }
        if (tid == 0) mn3[ax] = red[0];
        __syncthreads();
        red[tid] = p[ax];
        __syncthreads();
        for (int s = 256; s > 0; s >>= 1) {
            if (tid < s) red[tid] = fmaxf(red[tid], red[tid + s]);
            __syncthreads();
        }
        if (tid == 0) mx3[ax] = red[0];
        __syncthreads();
    }

    unsigned long long code = 0;
#pragma unroll
    for (int ax = 0; ax < 3; ax++) {
        float num = __fsub_rn(p[ax], mn3[ax]);
        float den = __fadd_rn(__fsub_rn(mx3[ax], mn3[ax]), 1e-8f);
        float nrm = div_rcp_rn(num, den);
        long long q = (long long)nrm;
        q *= 65535LL;
        if (q < 0) q = 0;
        if (q > 65535) q = 65535;
        unsigned long long m = (unsigned long long)q;
        m = (m | (m << 8)) & 0x00FF00FFull;
        m = (m | (m << 4)) & 0x0F0F0F0Full;
        m = (m | (m << 2)) & 0x33333333ull;
        m = (m | (m << 1)) & 0x55555555ull;
        code |= m << (2 - ax);
    }
    cod[tid] = code;
    __syncthreads();

    int rank = 0;
    for (int j = 0; j < 512; j++) {
        unsigned long long cj = cod[j];
        rank += (cj < code || (cj == code && j < tid)) ? 1 : 0;
    }

    const float* rr = d_y4 + ((size_t)b * S_ + tid) * 12;
    float s0 = p[0] * rr[0] + p[1] * rr[3] + p[2] * rr[6] + rr[9];
    float s1 = p[0] * rr[1] + p[1] * rr[4] + p[2] * rr[7] + rr[10];
    float s2 = p[0] * rr[2] + p[1] * rr[5] + p[2] * rr[8] + rr[11];

    float* o = out + ((size_t)b * (2 * S_) + 2 * (size_t)rank) * 3;
    o[0] = p[0]; o[1] = p[1]; o[2] = p[2];
    o[3] = s0;   o[4] = s1;   o[5] = s2;
}

// ---- launcher ----
extern "C" void kernel_launch(void* const* d_in, const int* in_sizes, int n_in,
                              void* d_out, int out_size) {
    (void)out_size;
    int map[15];
    {
        const int want[15] = {393216, 384, 64, 8192, 128, 32768, 256,
                              262144, 512, 131072, 256, 32768, 128, 1536, 12};
        bool dict_order = (n_in == 15);
        if (dict_order)
            for (int i = 0; i < 15; i++)
                if (in_sizes[i] != want[i]) { dict_order = false; break; }
        if (dict_order) {
            for (int i = 0; i < 15; i++) map[i] = i;
        } else {
            int used[64] = {0};
            for (int lo = 0; lo < 15; lo++) {
                map[lo] = 0;
                for (int i = 0; i < n_in && i < 64; i++)
                    if (!used[i] && in_sizes[i] == want[lo]) { map[lo] = i; used[i] = 1; break; }
            }
        }
    }
    const float* pc    = (const float*)d_in[map[0]];
    const float* w_sa1 = (const float*)d_in[map[1]];
    const float* b_sa1 = (const float*)d_in[map[2]];
    const float* w_sa2 = (const float*)d_in[map[3]];
    const float* b_sa2 = (const float*)d_in[map[4]];
    const float* w_sa3 = (const float*)d_in[map[5]];
    const float* b_sa3 = (const float*)d_in[map[6]];
    const float* w1 = (const float*)d_in[map[7]];
    const float* b1 = (const float*)d_in[map[8]];
    const float* w2 = (const float*)d_in[map[9]];
    const float* b2 = (const float*)d_in[map[10]];
    const float* w3 = (const float*)d_in[map[11]];
    const float* b3 = (const float*)d_in[map[12]];
    const float* w4 = (const float*)d_in[map[13]];
    const float* b4 = (const float*)d_in[map[14]];
    float* out = (float*)d_out;

    float *a1, *a2, *ft, *gfv, *y1, *y2, *y3, *y4;
    cudaGetSymbolAddress((void**)&a1,  d_a1);
    cudaGetSymbolAddress((void**)&a2,  d_a2);
    cudaGetSymbolAddress((void**)&ft,  d_ft);
    cudaGetSymbolAddress((void**)&gfv, d_gfv);
    cudaGetSymbolAddress((void**)&y1,  d_y1);
    cudaGetSymbolAddress((void**)&y2,  d_y2);
    cudaGetSymbolAddress((void**)&y3,  d_y3);
    cudaGetSymbolAddress((void**)&y4,  d_y4);

    k_fps<<<B_, 512>>>(pc);
    k_knn<<<dim3(16, B_), 256>>>(pc);
    k_sa1<<<NPTS / 256, 256>>>(pc, w_sa1, b_sa1);

    gemm_v5<1, 0, 0><<<dim3(NPTS / 128, 1), 256>>>(a1, w_sa2, b_sa2, a2, NPTS, 128, 64, nullptr);
    gemm_v5<1, 1, 0><<<dim3(NPTS / 128, 2), 256>>>(a2, w_sa3, b_sa3, ft, NPTS, 256, 128, nullptr);

    k_gf<<<B_, 256>>>();

    gemm_v5<2, 0, 1><<<dim3(NROW / 128, 4), 256>>>(ft, w1, b1, y1, NROW, 512, 512, gfv);
    gemm_v5<2, 0, 0><<<dim3(NROW / 128, 2), 256>>>(y1, w2, b2, y2, NROW, 256, 512, nullptr);
    gemm_v5<2, 0, 0><<<dim3(NROW / 128, 1), 256>>>(y2, w3, b3, y3, NROW, 128, 256, nullptr);
    gemm_v2<0><<<dim3(NROW / 64, 1), 256>>>(y3, w4, b4, y4, NROW, 12, 128);

    k_final<<<B_, 512>>>(out);
}